// round 8
// baseline (speedup 1.0000x reference)
#include <cuda_runtime.h>
#include <math.h>

#define NW 22

// R8: best shape (R4: 128 blocks x 1024 threads, 8 float4/thread) with
// micro-trims: abs folded into prologue, A-loads batched ahead of the
// store burst, streaming (evict-first) stores.
//
// Math (validated R2-R7):
//   out[4b+2i+j] = |TA[(b>>9)&1023]| * |TB[b&1023]| * S[c19,c0,c1,i,j]
//   b = (blk<<13)+(kk<<10)+t :
//     TB idx = t (tile-invariant), S idx from bits 0,18,19 (tile-invariant),
//     TA idx = warp-uniform, varies with kk.

__global__ void __launch_bounds__(1024) qk_fused(const float* __restrict__ x,
                                                 const float* __restrict__ y,
                                                 float4* __restrict__ out) {
    __shared__ float cx[NW], sx[NW], cy[NW], sy[NW];
    __shared__ float pc[NW], ps[NW];
    __shared__ float sTA[1024], sTB[1024];
    __shared__ float4 sS[8];
    const int t = threadIdx.x;

    if (t < NW) {
        float sxx, cxx, syy, cyy;
        __sincosf(0.5f * x[t], &sxx, &cxx);
        __sincosf(0.5f * y[t], &syy, &cyy);
        cx[t] = cxx; sx[t] = sxx; cy[t] = cyy; sy[t] = syy;
        pc[t] = cxx * cyy; ps[t] = sxx * syy;
    }
    __syncthreads();

    // One TA and one TB entry per thread; store |.| so the hot loop is abs-free.
    {
        int u = t ^ (t >> 1);
        float a = 1.0f, bb = 1.0f;
        #pragma unroll
        for (int j = 0; j < 9; ++j) {
            bool bit = (u >> j) & 1;
            a  *= bit ? ps[10 - j] : pc[10 - j];   // wires 2..10
            bb *= bit ? ps[19 - j] : pc[19 - j];   // wires 11..19
        }
        sTA[t] = fabsf(a);
        sTB[t] = fabsf(bb);
    }

    // S table: pre-contracted 2x2 matmul tail, stored as abs (entries >= 0).
    if (t < 32) {
        int j   =  t        & 1;
        int i   = (t >> 1)  & 1;
        int c1  = (t >> 2)  & 1;
        int c0  = (t >> 3)  & 1;
        int c19 = (t >> 4)  & 1;
        float s = 0.0f;
        #pragma unroll
        for (int k = 0; k < 2; ++k) {
            float ty = ((c19 ^ i)     ? sy[20] : cy[20])
                     * ((i   ^ k)     ? sy[21] : cy[21])
                     * ((c0  ^ k)     ? sy[0]  : cy[0])
                     * ((c0 ^ c1 ^ k) ? sy[1]  : cy[1]);
            float tx = ((c19 ^ k)     ? sx[20] : cx[20])
                     * ((k   ^ j)     ? sx[21] : cx[21])
                     * ((c0  ^ j)     ? sx[0]  : cx[0])
                     * ((c0 ^ c1 ^ j) ? sx[1]  : cx[1]);
            s += ty * tx;
        }
        reinterpret_cast<float*>(sS)[t] = fabsf(s);
    }
    __syncthreads();

    const unsigned base = (unsigned)blockIdx.x << 13;
    const unsigned b0 = base + (unsigned)t;
    const float4 s = sS[((b0 & 1u) << 2) | (((b0 >> 19) & 1u) << 1)
                        | ((b0 >> 18) & 1u)];
    const float B = sTB[t];                      // already |B|
    const float Bsx = B * s.x, Bsy = B * s.y, Bsz = B * s.z, Bsw = B * s.w;

    // Batch the 8 warp-uniform table reads, then fire 8 independent stores.
    float A[8];
    #pragma unroll
    for (int kk = 0; kk < 8; ++kk) {
        unsigned b = b0 + ((unsigned)kk << 10);
        A[kk] = sTA[(b >> 9) & 1023u];           // broadcast LDS, already |A|
    }

    #pragma unroll
    for (int kk = 0; kk < 8; ++kk) {
        float4 o;
        o.x = A[kk] * Bsx;
        o.y = A[kk] * Bsy;
        o.z = A[kk] * Bsz;
        o.w = A[kk] * Bsw;
        __stcs(&out[b0 + ((unsigned)kk << 10)], o);   // streaming STG.128
    }
}

extern "C" void kernel_launch(void* const* d_in, const int* in_sizes, int n_in,
                              void* d_out, int out_size) {
    const float* x = (const float*)d_in[0];
    const float* y = (const float*)d_in[1];
    // 2^20 float4 outputs / (1024 threads * 8 per thread) = 128 blocks
    qk_fused<<<128, 1024>>>(x, y, (float4*)d_out);
}

// round 9
// speedup vs baseline: 1.0036x; 1.0036x over previous
#include <cuda_runtime.h>
#include <math.h>

#define NW 22

// FINAL: fused single-kernel, 128 blocks x 1024 threads, 8 float4/thread.
// Confirmed at the chip's global write wall (~2.4 TB/s): R2-R8 showed kernel
// time is invariant (6.85-7.5us) across STG/TMA/hybrid stores, grid shapes,
// and cache policies. This is the best-measured configuration.
//
// Math (validated R2-R8, rel_err 3.5e-6):
//   out[4b+2i+j] = |TA[(b>>9)&1023]| * |TB[b&1023]| * S[c19,c0,c1,i,j]
//   b = (blk<<13)+(kk<<10)+t :
//     TB idx = t (tile-invariant), S idx from bits 0,18,19 (tile-invariant),
//     TA idx warp-uniform, varies with kk.

__global__ void __launch_bounds__(1024) qk_fused(const float* __restrict__ x,
                                                 const float* __restrict__ y,
                                                 float4* __restrict__ out) {
    __shared__ float cx[NW], sx[NW], cy[NW], sy[NW];
    __shared__ float pc[NW], ps[NW];
    __shared__ float sTA[1024], sTB[1024];
    __shared__ float4 sS[8];
    const int t = threadIdx.x;

    if (t < NW) {
        float sxx, cxx, syy, cyy;
        __sincosf(0.5f * x[t], &sxx, &cxx);
        __sincosf(0.5f * y[t], &syy, &cyy);
        cx[t] = cxx; sx[t] = sxx; cy[t] = cyy; sy[t] = syy;
        pc[t] = cxx * cyy; ps[t] = sxx * syy;
    }
    __syncthreads();

    // One TA and one TB entry per thread; store |.| so the hot loop is abs-free.
    {
        int u = t ^ (t >> 1);
        float a = 1.0f, bb = 1.0f;
        #pragma unroll
        for (int j = 0; j < 9; ++j) {
            bool bit = (u >> j) & 1;
            a  *= bit ? ps[10 - j] : pc[10 - j];   // wires 2..10
            bb *= bit ? ps[19 - j] : pc[19 - j];   // wires 11..19
        }
        sTA[t] = fabsf(a);
        sTB[t] = fabsf(bb);
    }

    // S table: pre-contracted 2x2 matmul tail, stored as abs (entries >= 0).
    if (t < 32) {
        int j   =  t        & 1;
        int i   = (t >> 1)  & 1;
        int c1  = (t >> 2)  & 1;
        int c0  = (t >> 3)  & 1;
        int c19 = (t >> 4)  & 1;
        float s = 0.0f;
        #pragma unroll
        for (int k = 0; k < 2; ++k) {
            float ty = ((c19 ^ i)     ? sy[20] : cy[20])
                     * ((i   ^ k)     ? sy[21] : cy[21])
                     * ((c0  ^ k)     ? sy[0]  : cy[0])
                     * ((c0 ^ c1 ^ k) ? sy[1]  : cy[1]);
            float tx = ((c19 ^ k)     ? sx[20] : cx[20])
                     * ((k   ^ j)     ? sx[21] : cx[21])
                     * ((c0  ^ j)     ? sx[0]  : cx[0])
                     * ((c0 ^ c1 ^ j) ? sx[1]  : cx[1]);
            s += ty * tx;
        }
        reinterpret_cast<float*>(sS)[t] = fabsf(s);
    }
    __syncthreads();

    const unsigned base = (unsigned)blockIdx.x << 13;
    const unsigned b0 = base + (unsigned)t;
    const float4 s = sS[((b0 & 1u) << 2) | (((b0 >> 19) & 1u) << 1)
                        | ((b0 >> 18) & 1u)];
    const float B = sTB[t];                      // already |B|
    const float Bsx = B * s.x, Bsy = B * s.y, Bsz = B * s.z, Bsw = B * s.w;

    // Batch the 8 warp-uniform table reads, then fire 8 independent stores.
    float A[8];
    #pragma unroll
    for (int kk = 0; kk < 8; ++kk) {
        unsigned b = b0 + ((unsigned)kk << 10);
        A[kk] = sTA[(b >> 9) & 1023u];           // broadcast LDS, already |A|
    }

    #pragma unroll
    for (int kk = 0; kk < 8; ++kk) {
        float4 o;
        o.x = A[kk] * Bsx;
        o.y = A[kk] * Bsy;
        o.z = A[kk] * Bsz;
        o.w = A[kk] * Bsw;
        out[b0 + ((unsigned)kk << 10)] = o;      // STG.128, fully coalesced
    }
}

extern "C" void kernel_launch(void* const* d_in, const int* in_sizes, int n_in,
                              void* d_out, int out_size) {
    const float* x = (const float*)d_in[0];
    const float* y = (const float*)d_in[1];
    // 2^20 float4 outputs / (1024 threads * 8 per thread) = 128 blocks
    qk_fused<<<128, 1024>>>(x, y, (float4*)d_out);
}

// round 10
// speedup vs baseline: 1.0370x; 1.0333x over previous
#include <cuda_runtime.h>
#include <math.h>

#define NW 22

// FINAL (= R4, empirically fastest: kernel 6.848us, total 8.64us).
// Single-wave fused kernel: 128 blocks x 1024 threads, 8 float4 outputs/thread.
// Confirmed at the chip's global write wall (~2.4 TB/s): R2-R9 showed kernel
// time invariant (6.85-7.5us) across STG/TMA/hybrid stores, grid shapes,
// cache policies, and instruction schedules. R4's interleaved LDS/STG loop
// measured best; R8/R9's batched-load variants measured consistently ~0.2us
// slower, so this restores the R4 schedule exactly.
//
// Math (validated R2-R9, rel_err 3.5e-6):
//   out[4b+2i+j] = |TA[(b>>9)&1023] * TB[b&1023]| * S[c19,c0,c1,i,j]
//   c19=b&1, c0=(b>>19)&1, c1=(b>>18)&1
//   TA indexed by c_1..c_10 (bit t = c_{10-t}),  wires 2..10
//   TB indexed by c_10..c_19 (bit t = c_{19-t}), wires 11..19
//   b_w = c_{w-1}^c_w  ->  u = v ^ (v>>1)
//
// Per thread (b = (blk<<13)+(k<<10)+t):
//   B-index = b & 1023 = t                      -> k-invariant, load once
//   sS-index uses bits 0,18,19 of b             -> k-invariant, load once
//   A-index = (b>>9)&1023, warp-uniform         -> 1 broadcast LDS per k

__global__ void __launch_bounds__(1024) qk_fused(const float* __restrict__ x,
                                                 const float* __restrict__ y,
                                                 float4* __restrict__ out) {
    __shared__ float cx[NW], sx[NW], cy[NW], sy[NW];
    __shared__ float pc[NW], ps[NW];       // pair products cx*cy, sx*sy
    __shared__ float sTA[1024], sTB[1024];
    __shared__ float4 sS[8];               // [c19][c0][c1] -> (i,j) quad
    const int t = threadIdx.x;

    if (t < NW) {
        float sxx, cxx, syy, cyy;
        __sincosf(0.5f * x[t], &sxx, &cxx);
        __sincosf(0.5f * y[t], &syy, &cyy);
        cx[t] = cxx; sx[t] = sxx; cy[t] = cyy; sy[t] = syy;
        pc[t] = cxx * cyy; ps[t] = sxx * syy;
    }
    __syncthreads();

    // Each thread fills one entry of each table.
    {
        int u = t ^ (t >> 1);
        float a = 1.0f, bb = 1.0f;
        #pragma unroll
        for (int j = 0; j < 9; ++j) {
            bool bit = (u >> j) & 1;
            a  *= bit ? ps[10 - j] : pc[10 - j];   // wires 2..10
            bb *= bit ? ps[19 - j] : pc[19 - j];   // wires 11..19
        }
        sTA[t] = a;
        sTB[t] = bb;
    }

    // S table: pre-contracted 2x2 matmul tail + abs (32 scalars).
    if (t < 32) {
        int j   =  t        & 1;
        int i   = (t >> 1)  & 1;
        int c1  = (t >> 2)  & 1;
        int c0  = (t >> 3)  & 1;
        int c19 = (t >> 4)  & 1;
        float s = 0.0f;
        #pragma unroll
        for (int k = 0; k < 2; ++k) {
            float ty = ((c19 ^ i)     ? sy[20] : cy[20])
                     * ((i   ^ k)     ? sy[21] : cy[21])
                     * ((c0  ^ k)     ? sy[0]  : cy[0])
                     * ((c0 ^ c1 ^ k) ? sy[1]  : cy[1]);
            float tx = ((c19 ^ k)     ? sx[20] : cx[20])
                     * ((k   ^ j)     ? sx[21] : cx[21])
                     * ((c0  ^ j)     ? sx[0]  : cx[0])
                     * ((c0 ^ c1 ^ j) ? sx[1]  : cx[1]);
            s += ty * tx;
        }
        reinterpret_cast<float*>(sS)[t] = fabsf(s);
    }
    __syncthreads();

    // Main loop: 8 coalesced float4 stores per thread.
    const unsigned base = (unsigned)blockIdx.x << 13;
    const float B = sTB[t];                                     // b&1023 == t
    const unsigned b0 = base + (unsigned)t;
    const float4 s = sS[((b0 & 1u) << 2) | (((b0 >> 19) & 1u) << 1)
                        | ((b0 >> 18) & 1u)];                   // k-invariant
    const float Bsx = B * s.x, Bsy = B * s.y, Bsz = B * s.z, Bsw = B * s.w;

    #pragma unroll
    for (int k = 0; k < 8; ++k) {
        unsigned b = b0 + ((unsigned)k << 10);
        float A = fabsf(sTA[(b >> 9) & 1023u]);                 // warp-uniform LDS
        float4 o;
        o.x = fabsf(A * Bsx);
        o.y = fabsf(A * Bsy);
        o.z = fabsf(A * Bsz);
        o.w = fabsf(A * Bsw);
        out[b] = o;
    }
}

extern "C" void kernel_launch(void* const* d_in, const int* in_sizes, int n_in,
                              void* d_out, int out_size) {
    const float* x = (const float*)d_in[0];
    const float* y = (const float*)d_in[1];
    // 2^20 float4 outputs / (1024 threads * 8 per thread) = 128 blocks
    qk_fused<<<128, 1024>>>(x, y, (float4*)d_out);
}